// round 10
// baseline (speedup 1.0000x reference)
#include <cuda_runtime.h>
#include <cuda_bf16.h>
#include <math.h>
#include <stdint.h>

// ---------------- problem constants ----------------
#define BSZ   8
#define DIM   384
#define HH    56
#define WW    56
#define HWQ   3136
#define NH    6
#define DH    64
#define GRP   3
#define NGD   128
#define HO    28
#define WO    28
#define LO    784
#define SCALE 0.125f

typedef unsigned short u16;

// ---------------- scratch (device globals, no allocs) ----------------
__device__ float  d_q  [(size_t)BSZ * DIM * HWQ];
__device__ u16    d_qh [(size_t)BSZ * DIM * HWQ];   // pre-scaled by SCALE
__device__ u16    d_ql [(size_t)BSZ * DIM * HWQ];
__device__ u16    d_xh [(size_t)BSZ * DIM * HWQ];
__device__ u16    d_xl [(size_t)BSZ * DIM * HWQ];
__device__ u16    d_wqh[DIM * DIM],     d_wql[DIM * DIM];
__device__ u16    d_wkh[2 * DIM * DIM], d_wkl[2 * DIM * DIM];
__device__ u16    d_wph[DIM * DIM],     d_wpl[DIM * DIM];
__device__ float  d_off [(size_t)BSZ * GRP * NGD * LO];
__device__ float4 d_grid[(size_t)BSZ * GRP * LO];
__device__ u16    d_xsh[(size_t)BSZ * DIM * LO],     d_xsl[(size_t)BSZ * DIM * LO];
__device__ u16    d_kvh[(size_t)BSZ * 2 * DIM * LO], d_kvl[(size_t)BSZ * 2 * DIM * LO];
__device__ u16    d_ah [(size_t)BSZ * HWQ * DIM],    d_al [(size_t)BSZ * HWQ * DIM];

// ---------------- helpers ----------------
__device__ __forceinline__ void split1(float x, u16& h, u16& l) {
    __nv_bfloat16 bh = __float2bfloat16(x);
    float r = x - __bfloat162float(bh);
    __nv_bfloat16 bl = __float2bfloat16(r);
    h = __bfloat16_as_ushort(bh);
    l = __bfloat16_as_ushort(bl);
}
__device__ __forceinline__ void split_pack(float x, float y, uint32_t& ph, uint32_t& pl) {
    u16 xh, xl, yh, yl;
    split1(x, xh, xl); split1(y, yh, yl);
    ph = ((uint32_t)yh << 16) | xh;
    pl = ((uint32_t)yl << 16) | xl;
}
__device__ __forceinline__ void mma_bf16(float* c, const uint32_t* a, const uint32_t* b) {
    asm volatile(
        "mma.sync.aligned.m16n8k16.row.col.f32.bf16.bf16.f32 "
        "{%0,%1,%2,%3}, {%4,%5,%6,%7}, {%8,%9}, {%0,%1,%2,%3};\n"
        : "+f"(c[0]), "+f"(c[1]), "+f"(c[2]), "+f"(c[3])
        : "r"(a[0]), "r"(a[1]), "r"(a[2]), "r"(a[3]), "r"(b[0]), "r"(b[1]));
}
__device__ __forceinline__ void ldsm4(uint32_t* r, const u16* p) {
    uint32_t a = (uint32_t)__cvta_generic_to_shared(p);
    asm volatile("ldmatrix.sync.aligned.m8n8.x4.shared.b16 {%0,%1,%2,%3}, [%4];"
                 : "=r"(r[0]), "=r"(r[1]), "=r"(r[2]), "=r"(r[3]) : "r"(a));
}
__device__ __forceinline__ void ldsm4t(uint32_t* r, const u16* p) {
    uint32_t a = (uint32_t)__cvta_generic_to_shared(p);
    asm volatile("ldmatrix.sync.aligned.m8n8.x4.trans.shared.b16 {%0,%1,%2,%3}, [%4];"
                 : "=r"(r[0]), "=r"(r[1]), "=r"(r[2]), "=r"(r[3]) : "r"(a));
}
// cp.async 16B with zero-fill when pred false
__device__ __forceinline__ void cpa16(u16* dst, const u16* src, bool pred) {
    uint32_t d = (uint32_t)__cvta_generic_to_shared(dst);
    int sz = pred ? 16 : 0;
    asm volatile("cp.async.cg.shared.global [%0], [%1], 16, %2;"
                 :: "r"(d), "l"(src), "r"(sz));
}
#define CPA_COMMIT asm volatile("cp.async.commit_group;" ::: "memory")
#define CPA_WAIT0  asm volatile("cp.async.wait_group 0;" ::: "memory")

// ---------------- f32 -> (hi,lo) bf16 split ----------------
__global__ void split_kernel(const float* __restrict__ src, u16* __restrict__ h,
                             u16* __restrict__ l, int n4) {
    int i = blockIdx.x * blockDim.x + threadIdx.x;
    if (i >= n4) return;
    float4 v = ((const float4*)src)[i];
    ushort4 hh, ll;
    split1(v.x, hh.x, ll.x); split1(v.y, hh.y, ll.y);
    split1(v.z, hh.z, ll.z); split1(v.w, hh.w, ll.w);
    ((ushort4*)h)[i] = hh; ((ushort4*)l)[i] = ll;
}

// ==================================================================
// GEMM: Y[b] = W(MxK=384) @ X[b](384xN), pre-split bf16 operands,
// cp.async double-buffered. Rows m0<thr2 use 2-term split.
// ==================================================================
#define SST 24
#define BNS 136
#define GBUF (128 * SST)
template<bool BT, bool WF32, bool WSPLIT>
__global__ __launch_bounds__(256, 2) void gemm_bf16(
    const u16* __restrict__ Wh, const u16* __restrict__ Wl,
    const u16* __restrict__ Xh, const u16* __restrict__ Xl,
    float* __restrict__ Yf, u16* __restrict__ Ysh, u16* __restrict__ Ysl,
    const float* __restrict__ bias, int M, int N, int thr2, float spscale) {
    const int KD = 384;
    __shared__ __align__(16) u16 Ah[2 * GBUF], Al[2 * GBUF];
    __shared__ __align__(16) u16 Bh[2 * GBUF], Bl[2 * GBUF];
    const int bz = blockIdx.z;
    const size_t xoff = (size_t)bz * KD * N;
    const int m0 = blockIdx.y * 128, n0 = blockIdx.x * 128;
    const int tid = threadIdx.x, lane = tid & 31, wid = tid >> 5;
    const int wm = wid & 3, wn = wid >> 2;
    const bool full3 = (m0 >= thr2);
    float c[2][8][4] = {};

    const int arow = tid >> 1, acol = (tid & 1) * 8;
    const int bro = tid >> 4, bcol = (tid & 15) * 8;   // NN
    const int bn2 = tid >> 1, bk2 = (tid & 1) * 8;     // BT

    auto STAGE = [&](int kc, int buf) {
        size_t ao = (size_t)(m0 + arow) * KD + kc * 16 + acol;
        cpa16(&Ah[buf * GBUF + arow * SST + acol], &Wh[ao], true);
        cpa16(&Al[buf * GBUF + arow * SST + acol], &Wl[ao], true);
        if (!BT) {
            bool v = (n0 + bcol) < N;
            size_t o = xoff + (size_t)(kc * 16 + bro) * N + n0 + bcol;
            cpa16(&Bh[buf * GBUF + bro * BNS + bcol], v ? &Xh[o] : Xh, v);
            cpa16(&Bl[buf * GBUF + bro * BNS + bcol], v ? &Xl[o] : Xl, v);
        } else {
            bool v = (n0 + bn2) < N;
            size_t o = xoff + (size_t)(n0 + bn2) * KD + kc * 16 + bk2;
            cpa16(&Bh[buf * GBUF + bn2 * SST + bk2], v ? &Xh[o] : Xh, v);
            cpa16(&Bl[buf * GBUF + bn2 * SST + bk2], v ? &Xl[o] : Xl, v);
        }
    };

    STAGE(0, 0); CPA_COMMIT;
    const int afr = wm * 32 + (lane & 15);
    const int afc = (lane >> 4) << 3;
    for (int kc = 0; kc < 24; kc++) {
        const int buf = kc & 1;
        CPA_WAIT0;
        __syncthreads();
        if (kc < 23) { STAGE(kc + 1, buf ^ 1); CPA_COMMIT; }
        uint32_t ah[2][4], al[2][4];
        #pragma unroll
        for (int mt = 0; mt < 2; mt++) {
            ldsm4(ah[mt], &Ah[buf * GBUF + (afr + mt * 16) * SST + afc]);
            ldsm4(al[mt], &Al[buf * GBUF + (afr + mt * 16) * SST + afc]);
        }
        #pragma unroll
        for (int p = 0; p < 4; p++) {
            uint32_t bh4[4], bl4[4];
            if (!BT) {
                int r = lane & 15, cN = wn * 64 + p * 16 + afc;
                ldsm4t(bh4, &Bh[buf * GBUF + r * BNS + cN]);
                ldsm4t(bl4, &Bl[buf * GBUF + r * BNS + cN]);
            } else {
                int r = wn * 64 + p * 16 + (lane & 7) + afc;
                int cK = ((lane >> 3) & 1) << 3;
                ldsm4(bh4, &Bh[buf * GBUF + r * SST + cK]);
                ldsm4(bl4, &Bl[buf * GBUF + r * SST + cK]);
            }
            #pragma unroll
            for (int sub = 0; sub < 2; sub++) {
                int nt = 2 * p + sub;
                #pragma unroll
                for (int mt = 0; mt < 2; mt++) {
                    mma_bf16(c[mt][nt], ah[mt], &bh4[2 * sub]);
                    mma_bf16(c[mt][nt], al[mt], &bh4[2 * sub]);
                    if (full3) mma_bf16(c[mt][nt], ah[mt], &bl4[2 * sub]);
                }
            }
        }
        __syncthreads();
    }

    const int g = lane >> 2, tq = lane & 3;
    #pragma unroll
    for (int mt = 0; mt < 2; mt++) {
        int row0 = m0 + wm * 32 + mt * 16 + g;
        int row1 = row0 + 8;
        float bv0 = bias ? bias[row0] : 0.f;
        float bv1 = bias ? bias[row1] : 0.f;
        #pragma unroll
        for (int nt = 0; nt < 8; nt++) {
            int col = n0 + wn * 64 + nt * 8 + 2 * tq;
            if (col < N) {
                float v00 = c[mt][nt][0] + bv0, v01 = c[mt][nt][1] + bv0;
                float v10 = c[mt][nt][2] + bv1, v11 = c[mt][nt][3] + bv1;
                size_t o0 = (size_t)bz * M * N + (size_t)row0 * N + col;
                size_t o1 = (size_t)bz * M * N + (size_t)row1 * N + col;
                if (WF32) {
                    *(float2*)&Yf[o0] = make_float2(v00, v01);
                    *(float2*)&Yf[o1] = make_float2(v10, v11);
                }
                if (WSPLIT) {
                    u16 h0, l0, h1, l1;
                    split1(v00 * spscale, h0, l0); split1(v01 * spscale, h1, l1);
                    *(uint32_t*)&Ysh[o0] = ((uint32_t)h1 << 16) | h0;
                    *(uint32_t*)&Ysl[o0] = ((uint32_t)l1 << 16) | l0;
                    split1(v10 * spscale, h0, l0); split1(v11 * spscale, h1, l1);
                    *(uint32_t*)&Ysh[o1] = ((uint32_t)h1 << 16) | h0;
                    *(uint32_t*)&Ysl[o1] = ((uint32_t)l1 << 16) | l0;
                }
            }
        }
    }
}

// ==================================================================
// Fused flash attention: 64q x 64k tiles, 4 warps, 2-term QK, 3-term PV.
// Smem: 2 KV bufs; Q staging region ALIASES buf1 (dead after frag loads).
// Occupancy 4 via launch_bounds(128,4). Last tile skips dead mmas.
// ==================================================================
#define AS 72
#define KVB (3 * 64 * AS)   // u16 units per KV buffer (Kh,Vh,Vl)
__global__ __launch_bounds__(128, 4) void attn_bf16(
    const u16* __restrict__ qh, const u16* __restrict__ ql,
    const u16* __restrict__ kvh, const u16* __restrict__ kvl,
    u16* __restrict__ oh, u16* __restrict__ ol) {
    extern __shared__ __align__(16) u16 smx[];
    u16* KV = smx;              // buf b at KV + b*KVB
    u16* Qh = smx + KVB;        // aliases buf1 (written only from t=0 stage, after frag loads)
    u16* Ql = Qh + 64 * AS;
    const int qb = blockIdx.x * 64, h = blockIdx.y, b = blockIdx.z;
    const int tid = threadIdx.x, lane = tid & 31, wid = tid >> 5;
    const int g = lane >> 2, tq = lane & 3;
    const size_t qoff = ((size_t)(b * DIM + h * DH)) * HWQ + qb;
    const size_t koff = ((size_t)(b * 2 * DIM + h * DH)) * LO;
    const size_t voff = ((size_t)(b * 2 * DIM + DIM + h * DH)) * LO;

    auto STAGE_KV = [&](int t, int buf) {
        u16* Kh = KV + buf * KVB;
        u16* Vh = Kh + 64 * AS;
        u16* Vl = Vh + 64 * AS;
        for (int i = tid; i < 512; i += 128) {
            int d = i >> 3, c8 = (i & 7) * 8;
            int key = t * 64 + c8;
            bool v = key < LO;
            size_t gk = koff + (size_t)d * LO + key;
            size_t gv = voff + (size_t)d * LO + key;
            cpa16(&Kh[d * AS + c8], v ? &kvh[gk] : kvh, v);
            cpa16(&Vh[d * AS + c8], v ? &kvh[gv] : kvh, v);
            cpa16(&Vl[d * AS + c8], v ? &kvl[gv] : kvl, v);
        }
    };

    // stage Q [q][d] into the region aliasing buf1
    for (int i = tid; i < 4096; i += 128) {
        int d = i >> 6, qq = i & 63;
        Qh[qq * AS + d] = qh[qoff + (size_t)d * HWQ + qq];
        Ql[qq * AS + d] = ql[qoff + (size_t)d * HWQ + qq];
    }
    STAGE_KV(0, 0); CPA_COMMIT;   // buf0 does not alias Q
    __syncthreads();
    uint32_t qfh[4][4], qfl[4][4];
    const int afr = wid * 16 + (lane & 15);
    const int afc = (lane >> 4) << 3;
    #pragma unroll
    for (int kc = 0; kc < 4; kc++) {
        ldsm4(qfh[kc], &Qh[afr * AS + kc * 16 + afc]);
        ldsm4(qfl[kc], &Ql[afr * AS + kc * 16 + afc]);
    }

    float o[8][4] = {};
    float mrow0 = -1e30f, mrow1 = -1e30f, lrow0 = 0.f, lrow1 = 0.f;

    for (int t = 0; t < 13; t++) {
        const int buf = t & 1;
        u16* Kh = KV + buf * KVB;
        u16* Vh = Kh + 64 * AS;
        u16* Vl = Vh + 64 * AS;
        CPA_WAIT0;
        __syncthreads();
        // t=0: this sync also orders all warps' Q-frag ldsm before buf1 (alias) is written
        if (t < 12) { STAGE_KV(t + 1, buf ^ 1); CPA_COMMIT; }

        const int pmax = (t == 12) ? 1 : 4;   // valid keys on last tile: 768..783 (chunk 0)
        float s[8][4] = {};
        #pragma unroll
        for (int kc = 0; kc < 4; kc++) {
            #pragma unroll
            for (int p = 0; p < 4; p++) {
                if (p >= pmax) break;
                uint32_t bh4[4];
                int r = kc * 16 + (lane & 15), cN = p * 16 + afc;
                ldsm4t(bh4, &Kh[r * AS + cN]);
                #pragma unroll
                for (int sub = 0; sub < 2; sub++) {
                    int nt = 2 * p + sub;
                    mma_bf16(s[nt], qfh[kc], &bh4[2 * sub]);
                    mma_bf16(s[nt], qfl[kc], &bh4[2 * sub]);
                }
            }
        }
        if (t == 12) {
            #pragma unroll
            for (int nt = 0; nt < 8; nt++) {
                int key0 = 768 + nt * 8 + 2 * tq;
                if (key0 >= LO) { s[nt][0] = s[nt][1] = s[nt][2] = s[nt][3] = -1e30f; }
            }
        }
        // online softmax (rows g, g+8)
        float mx0 = -1e30f, mx1 = -1e30f;
        #pragma unroll
        for (int nt = 0; nt < 8; nt++) {
            mx0 = fmaxf(mx0, fmaxf(s[nt][0], s[nt][1]));
            mx1 = fmaxf(mx1, fmaxf(s[nt][2], s[nt][3]));
        }
        mx0 = fmaxf(mx0, __shfl_xor_sync(0xffffffffu, mx0, 1));
        mx0 = fmaxf(mx0, __shfl_xor_sync(0xffffffffu, mx0, 2));
        mx1 = fmaxf(mx1, __shfl_xor_sync(0xffffffffu, mx1, 1));
        mx1 = fmaxf(mx1, __shfl_xor_sync(0xffffffffu, mx1, 2));
        float nm0 = fmaxf(mrow0, mx0), nm1 = fmaxf(mrow1, mx1);
        float corr0 = __expf(mrow0 - nm0), corr1 = __expf(mrow1 - nm1);
        mrow0 = nm0; mrow1 = nm1;
        float ps0 = 0.f, ps1 = 0.f;
        #pragma unroll
        for (int nt = 0; nt < 8; nt++) {
            s[nt][0] = __expf(s[nt][0] - nm0); ps0 += s[nt][0];
            s[nt][1] = __expf(s[nt][1] - nm0); ps0 += s[nt][1];
            s[nt][2] = __expf(s[nt][2] - nm1); ps1 += s[nt][2];
            s[nt][3] = __expf(s[nt][3] - nm1); ps1 += s[nt][3];
        }
        ps0 += __shfl_xor_sync(0xffffffffu, ps0, 1);
        ps0 += __shfl_xor_sync(0xffffffffu, ps0, 2);
        ps1 += __shfl_xor_sync(0xffffffffu, ps1, 1);
        ps1 += __shfl_xor_sync(0xffffffffu, ps1, 2);
        lrow0 = lrow0 * corr0 + ps0;
        lrow1 = lrow1 * corr1 + ps1;
        #pragma unroll
        for (int nt = 0; nt < 8; nt++) {
            o[nt][0] *= corr0; o[nt][1] *= corr0;
            o[nt][2] *= corr1; o[nt][3] *= corr1;
        }
        // P fragments + PV (3-term). Last tile: only key-chunk kc=0 has p != 0.
        const int kcmax = (t == 12) ? 1 : 4;
        uint32_t ph[4][4], pl[4][4];
        #pragma unroll
        for (int kc = 0; kc < 4; kc++) {
            if (kc >= kcmax) break;
            split_pack(s[2 * kc][0],     s[2 * kc][1],     ph[kc][0], pl[kc][0]);
            split_pack(s[2 * kc][2],     s[2 * kc][3],     ph[kc][1], pl[kc][1]);
            split_pack(s[2 * kc + 1][0], s[2 * kc + 1][1], ph[kc][2], pl[kc][2]);
            split_pack(s[2 * kc + 1][2], s[2 * kc + 1][3], ph[kc][3], pl[kc][3]);
        }
        #pragma unroll
        for (int kc = 0; kc < 4; kc++) {
            if (kc >= kcmax) break;
            #pragma unroll
            for (int p = 0; p < 4; p++) {
                uint32_t vh4[4], vl4[4];
                int vr = p * 16 + (lane & 7) + afc;
                int vc = kc * 16 + (((lane >> 3) & 1) << 3);
                ldsm4(vh4, &Vh[vr * AS + vc]);
                ldsm4(vl4, &Vl[vr * AS + vc]);
                #pragma unroll
                for (int sub = 0; sub < 2; sub++) {
                    int nt = 2 * p + sub;
                    mma_bf16(o[nt], ph[kc], &vh4[2 * sub]);
                    mma_bf16(o[nt], pl[kc], &vh4[2 * sub]);
                    mma_bf16(o[nt], ph[kc], &vl4[2 * sub]);
                }
            }
        }
        __syncthreads();
    }
    float inv0 = 1.f / lrow0, inv1 = 1.f / lrow1;
    size_t base = (size_t)b * HWQ + qb;
    int rlo = wid * 16 + g, rhi = rlo + 8;
    #pragma unroll
    for (int nt = 0; nt < 8; nt++) {
        int d = h * DH + nt * 8 + 2 * tq;
        u16 h0, l0, h1, l1;
        split1(o[nt][0] * inv0, h0, l0); split1(o[nt][1] * inv0, h1, l1);
        *(uint32_t*)&oh[(base + rlo) * DIM + d] = ((uint32_t)h1 << 16) | h0;
        *(uint32_t*)&ol[(base + rlo) * DIM + d] = ((uint32_t)l1 << 16) | l0;
        split1(o[nt][2] * inv1, h0, l0); split1(o[nt][3] * inv1, h1, l1);
        *(uint32_t*)&oh[(base + rhi) * DIM + d] = ((uint32_t)h1 << 16) | h0;
        *(uint32_t*)&ol[(base + rhi) * DIM + d] = ((uint32_t)l1 << 16) | l0;
    }
}

// ---------------- depthwise 5x5 s2 + bias + BN + exact GELU ----------------
__global__ void dw_bn_gelu_kernel(const float* __restrict__ q,
                                  const float* __restrict__ dw_w, const float* __restrict__ dw_b,
                                  const float* __restrict__ bn_w, const float* __restrict__ bn_b,
                                  const float* __restrict__ bn_mean, const float* __restrict__ bn_var,
                                  float* __restrict__ off) {
    int idx = blockIdx.x * blockDim.x + threadIdx.x;
    const int TOT = BSZ * GRP * NGD * LO;
    if (idx >= TOT) return;
    int pix = idx % LO;
    int c   = (idx / LO) % NGD;
    int n   = idx / (LO * NGD);
    int oy = pix / WO, ox = pix % WO;
    int b = n / GRP, g = n % GRP;
    const float* plane = q + ((size_t)(b * DIM + g * NGD + c)) * HWQ;
    const float* wk = dw_w + c * 25;
    float s = 0.f;
    #pragma unroll
    for (int ky = 0; ky < 5; ky++) {
        int iy = oy * 2 + ky - 2;
        if (iy < 0 || iy >= HH) continue;
        #pragma unroll
        for (int kx = 0; kx < 5; kx++) {
            int ix = ox * 2 + kx - 2;
            if (ix >= 0 && ix < WW) s = fmaf(plane[iy * WW + ix], wk[ky * 5 + kx], s);
        }
    }
    s += dw_b[c];
    s = (s - bn_mean[c]) * (bn_w[c] * rsqrtf(bn_var[c] + 1e-6f)) + bn_b[c];
    s = 0.5f * s * (1.0f + erff(s * 0.70710678118654752f));
    off[idx] = s;
}

// ---------------- pointwise 128->3 + offset/grid math ----------------
__global__ void pw_grid_kernel(const float* __restrict__ off, const float* __restrict__ pw_w,
                               float4* __restrict__ grid4) {
    int idx = blockIdx.x * blockDim.x + threadIdx.x;
    const int TOT = BSZ * GRP * LO;
    if (idx >= TOT) return;
    int n = idx / LO, pix = idx % LO;
    const float* base = off + (size_t)n * NGD * LO + pix;
    float o0 = 0.f, o1 = 0.f, o2 = 0.f;
    #pragma unroll 4
    for (int c = 0; c < NGD; c++) {
        float v = base[(size_t)c * LO];
        o0 = fmaf(v, pw_w[c], o0);
        o1 = fmaf(v, pw_w[NGD + c], o1);
        o2 = fmaf(v, pw_w[2 * NGD + c], o2);
    }
    int oy = pix / WO, ox = pix % WO;
    float ry = ((0.5f + (float)oy) / (float)HO) * 2.f - 1.f;
    float rx = ((0.5f + (float)ox) / (float)WO) * 2.f - 1.f;
    float posy = tanhf(o0) * (2.0f / (float)HO) + ry;
    float posx = tanhf(o1) * (2.0f / (float)WO) + rx;
    float gx = (posx + 1.f) * 0.5f * (float)(WW - 1);
    float gy = (posy + 1.f) * 0.5f * (float)(HH - 1);
    float sig = 1.f / (1.f + expf(-o2));
    float mod = 1.f / (1.f + expf(-sig));
    grid4[idx] = make_float4(gx, gy, mod, 0.f);
}

// ---------------- bilinear grid sample * modulation -> split bf16 ----------------
__global__ void sample_kernel(const float* __restrict__ x, const float4* __restrict__ grid4,
                              u16* __restrict__ xsh, u16* __restrict__ xsl) {
    int nc = blockIdx.x;
    int pix = blockIdx.y * blockDim.x + threadIdx.x;
    if (pix >= LO) return;
    int c = nc & (NGD - 1), n = nc >> 7;
    int b = n / GRP, g = n % GRP;
    float4 gq = grid4[(size_t)n * LO + pix];
    float gx = gq.x, gy = gq.y, mod = gq.z;
    float x0f = floorf(gx), y0f = floorf(gy);
    float x1f = x0f + 1.f, y1f = y0f + 1.f;
    const float* plane = x + ((size_t)(b * DIM + g * NGD + c)) * HWQ;

    float t00 = 0.f, t01 = 0.f, t10 = 0.f, t11 = 0.f;
    bool vx0 = (x0f >= 0.f) && (x0f <= (float)(WW - 1));
    bool vx1 = (x1f >= 0.f) && (x1f <= (float)(WW - 1));
    bool vy0 = (y0f >= 0.f) && (y0f <= (float)(HH - 1));
    bool vy1 = (y1f >= 0.f) && (y1f <= (float)(HH - 1));
    int xi0 = (int)fminf(fmaxf(x0f, 0.f), (float)(WW - 1));
    int xi1 = (int)fminf(fmaxf(x1f, 0.f), (float)(WW - 1));
    int yi0 = (int)fminf(fmaxf(y0f, 0.f), (float)(HH - 1));
    int yi1 = (int)fminf(fmaxf(y1f, 0.f), (float)(HH - 1));
    if (vy0 && vx0) t00 = plane[yi0 * WW + xi0];
    if (vy1 && vx0) t10 = plane[yi1 * WW + xi0];
    if (vy0 && vx1) t01 = plane[yi0 * WW + xi1];
    if (vy1 && vx1) t11 = plane[yi1 * WW + xi1];

    float v = t00 * (x1f - gx) * (y1f - gy)
            + t10 * (x1f - gx) * (gy - y0f)
            + t01 * (gx - x0f) * (y1f - gy)
            + t11 * (gx - x0f) * (gy - y0f);
    v *= mod;
    u16 hh, ll; split1(v, hh, ll);
    size_t o = ((size_t)(b * DIM + g * NGD + c)) * LO + pix;
    xsh[o] = hh; xsl[o] = ll;
}

// ---------------- launch ----------------
extern "C" void kernel_launch(void* const* d_in, const int* in_sizes, int n_in,
                              void* d_out, int out_size) {
    const float* x      = (const float*)d_in[0];
    const float* q_w    = (const float*)d_in[1];
    const float* kv_w   = (const float*)d_in[2];
    const float* proj_w = (const float*)d_in[3];
    const float* proj_b = (const float*)d_in[4];
    const float* dw_w   = (const float*)d_in[5];
    const float* dw_b   = (const float*)d_in[6];
    const float* bn_w   = (const float*)d_in[7];
    const float* bn_b   = (const float*)d_in[8];
    const float* bn_mean= (const float*)d_in[9];
    const float* bn_var = (const float*)d_in[10];
    const float* pw_w   = (const float*)d_in[11];
    float* out = (float*)d_out;

    float *q, *off; float4* grid;
    u16 *qh, *ql, *xh, *xl, *wqh, *wql, *wkh, *wkl, *wph, *wpl;
    u16 *xsh, *xsl, *kvh, *kvl, *ah, *al;
    cudaGetSymbolAddress((void**)&q,    d_q);
    cudaGetSymbolAddress((void**)&off,  d_off);
    cudaGetSymbolAddress((void**)&grid, d_grid);
    cudaGetSymbolAddress((void**)&qh,   d_qh);
    cudaGetSymbolAddress((void**)&ql,   d_ql);
    cudaGetSymbolAddress((void**)&xh,   d_xh);
    cudaGetSymbolAddress((void**)&xl,   d_xl);
    cudaGetSymbolAddress((void**)&wqh,  d_wqh);
    cudaGetSymbolAddress((void**)&wql,  d_wql);
    cudaGetSymbolAddress((void**)&wkh,  d_wkh);
    cudaGetSymbolAddress((void**)&wkl,  d_wkl);
    cudaGetSymbolAddress((void**)&wph,  d_wph);
    cudaGetSymbolAddress((void**)&wpl,  d_wpl);
    cudaGetSymbolAddress((void**)&xsh,  d_xsh);
    cudaGetSymbolAddress((void**)&xsl,  d_xsl);
    cudaGetSymbolAddress((void**)&kvh,  d_kvh);
    cudaGetSymbolAddress((void**)&kvl,  d_kvl);
    cudaGetSymbolAddress((void**)&ah,   d_ah);
    cudaGetSymbolAddress((void**)&al,   d_al);

    // pre-split x and weights
    {
        int n4 = BSZ * DIM * HWQ / 4;
        split_kernel<<<(n4 + 255) / 256, 256>>>(x, xh, xl, n4);
        int w4 = DIM * DIM / 4;
        split_kernel<<<(w4 + 255) / 256, 256>>>(q_w, wqh, wql, w4);
        split_kernel<<<(2 * w4 + 255) / 256, 256>>>(kv_w, wkh, wkl, 2 * w4);
        split_kernel<<<(w4 + 255) / 256, 256>>>(proj_w, wph, wpl, w4);
    }
    // K1: q = q_w @ x  -> f32 + split (Q split pre-scaled by SCALE)
    {
        dim3 g1((HWQ + 127) / 128, DIM / 128, BSZ);
        gemm_bf16<false, true, true><<<g1, 256>>>(wqh, wql, xh, xl, q, qh, ql,
                                                  nullptr, DIM, HWQ, 0, SCALE);
    }
    // K2: depthwise conv + bias + BN + gelu
    {
        int tot = BSZ * GRP * NGD * LO;
        dw_bn_gelu_kernel<<<(tot + 255) / 256, 256>>>(q, dw_w, dw_b, bn_w, bn_b,
                                                      bn_mean, bn_var, off);
    }
    // K3a: pointwise + grid
    {
        int tot = BSZ * GRP * LO;
        pw_grid_kernel<<<(tot + 255) / 256, 256>>>(off, pw_w, grid);
    }
    // K3b: bilinear sampling -> xs split
    {
        dim3 g((BSZ * GRP * NGD), (LO + 255) / 256);
        sample_kernel<<<g, 256>>>(x, grid, xsh, xsl);
    }
    // K4: kv = kv_w @ xs -> split only (k-half m0<384 uses 2-term)
    {
        dim3 g((LO + 127) / 128, (2 * DIM) / 128, BSZ);
        gemm_bf16<false, false, true><<<g, 256>>>(wkh, wkl, xsh, xsl, nullptr,
                                                  kvh, kvl, nullptr, 2 * DIM, LO, DIM, 1.0f);
    }
    // K5: fused attention (64q tiles, occ 4 via smem aliasing) -> attn split
    {
        dim3 g(HWQ / 64, NH, BSZ);
        size_t smem = (size_t)(2 * KVB) * sizeof(u16);  // 55296 B
        cudaFuncSetAttribute(attn_bf16, cudaFuncAttributeMaxDynamicSharedMemorySize, (int)smem);
        attn_bf16<<<g, 128, smem>>>(qh, ql, kvh, kvl, ah, al);
    }
    // K6: out = proj_w @ attn^T + proj_b  (3-term)
    {
        dim3 g1((HWQ + 127) / 128, DIM / 128, BSZ);
        gemm_bf16<true, true, false><<<g1, 256>>>(wph, wpl, ah, al, out,
                                                  nullptr, nullptr, proj_b, DIM, HWQ, 0, 1.0f);
    }
}

// round 12
// speedup vs baseline: 1.0645x; 1.0645x over previous
#include <cuda_runtime.h>
#include <cuda_bf16.h>
#include <math.h>
#include <stdint.h>

// ---------------- problem constants ----------------
#define BSZ   8
#define DIM   384
#define HH    56
#define WW    56
#define HWQ   3136
#define NH    6
#define DH    64
#define GRP   3
#define NGD   128
#define HO    28
#define WO    28
#define LO    784
#define SCALE 0.125f

typedef unsigned short u16;

// ---------------- scratch (device globals, no allocs) ----------------
__device__ float  d_q  [(size_t)BSZ * DIM * HWQ];
__device__ u16    d_qh [(size_t)BSZ * DIM * HWQ];   // pre-scaled by SCALE
__device__ u16    d_ql [(size_t)BSZ * DIM * HWQ];
__device__ u16    d_xh [(size_t)BSZ * DIM * HWQ];
__device__ u16    d_xl [(size_t)BSZ * DIM * HWQ];
__device__ u16    d_wqh[DIM * DIM],     d_wql[DIM * DIM];
__device__ u16    d_wkh[2 * DIM * DIM], d_wkl[2 * DIM * DIM];
__device__ u16    d_wph[DIM * DIM],     d_wpl[DIM * DIM];
__device__ float  d_off [(size_t)BSZ * GRP * NGD * LO];
__device__ float4 d_grid[(size_t)BSZ * GRP * LO];
__device__ u16    d_xsh[(size_t)BSZ * DIM * LO],     d_xsl[(size_t)BSZ * DIM * LO];
__device__ u16    d_kvh[(size_t)BSZ * 2 * DIM * LO], d_kvl[(size_t)BSZ * 2 * DIM * LO];
__device__ u16    d_ah [(size_t)BSZ * HWQ * DIM],    d_al [(size_t)BSZ * HWQ * DIM];

// ---------------- helpers ----------------
__device__ __forceinline__ void split1(float x, u16& h, u16& l) {
    __nv_bfloat16 bh = __float2bfloat16(x);
    float r = x - __bfloat162float(bh);
    __nv_bfloat16 bl = __float2bfloat16(r);
    h = __bfloat16_as_ushort(bh);
    l = __bfloat16_as_ushort(bl);
}
__device__ __forceinline__ void split_pack(float x, float y, uint32_t& ph, uint32_t& pl) {
    u16 xh, xl, yh, yl;
    split1(x, xh, xl); split1(y, yh, yl);
    ph = ((uint32_t)yh << 16) | xh;
    pl = ((uint32_t)yl << 16) | xl;
}
__device__ __forceinline__ void mma_bf16(float* c, const uint32_t* a, const uint32_t* b) {
    asm volatile(
        "mma.sync.aligned.m16n8k16.row.col.f32.bf16.bf16.f32 "
        "{%0,%1,%2,%3}, {%4,%5,%6,%7}, {%8,%9}, {%0,%1,%2,%3};\n"
        : "+f"(c[0]), "+f"(c[1]), "+f"(c[2]), "+f"(c[3])
        : "r"(a[0]), "r"(a[1]), "r"(a[2]), "r"(a[3]), "r"(b[0]), "r"(b[1]));
}
__device__ __forceinline__ void ldsm4(uint32_t* r, const u16* p) {
    uint32_t a = (uint32_t)__cvta_generic_to_shared(p);
    asm volatile("ldmatrix.sync.aligned.m8n8.x4.shared.b16 {%0,%1,%2,%3}, [%4];"
                 : "=r"(r[0]), "=r"(r[1]), "=r"(r[2]), "=r"(r[3]) : "r"(a));
}
__device__ __forceinline__ void ldsm4t(uint32_t* r, const u16* p) {
    uint32_t a = (uint32_t)__cvta_generic_to_shared(p);
    asm volatile("ldmatrix.sync.aligned.m8n8.x4.trans.shared.b16 {%0,%1,%2,%3}, [%4];"
                 : "=r"(r[0]), "=r"(r[1]), "=r"(r[2]), "=r"(r[3]) : "r"(a));
}
// cp.async 16B with zero-fill when pred false
__device__ __forceinline__ void cpa16(u16* dst, const u16* src, bool pred) {
    uint32_t d = (uint32_t)__cvta_generic_to_shared(dst);
    int sz = pred ? 16 : 0;
    asm volatile("cp.async.cg.shared.global [%0], [%1], 16, %2;"
                 :: "r"(d), "l"(src), "r"(sz));
}
#define CPA_COMMIT asm volatile("cp.async.commit_group;" ::: "memory")
#define CPA_WAIT0  asm volatile("cp.async.wait_group 0;" ::: "memory")

// ---------------- f32 -> (hi,lo) bf16 split ----------------
__global__ void split_kernel(const float* __restrict__ src, u16* __restrict__ h,
                             u16* __restrict__ l, int n4) {
    int i = blockIdx.x * blockDim.x + threadIdx.x;
    if (i >= n4) return;
    float4 v = ((const float4*)src)[i];
    ushort4 hh, ll;
    split1(v.x, hh.x, ll.x); split1(v.y, hh.y, ll.y);
    split1(v.z, hh.z, ll.z); split1(v.w, hh.w, ll.w);
    ((ushort4*)h)[i] = hh; ((ushort4*)l)[i] = ll;
}

// ==================================================================
// GEMM: Y[b] = W(MxK=384) @ X[b](384xN), pre-split bf16 operands,
// cp.async double-buffered. Rows m0<thr2 use 2-term split.
// ==================================================================
#define SST 24
#define BNS 136
#define GBUF (128 * SST)
template<bool BT, bool WF32, bool WSPLIT>
__global__ __launch_bounds__(256, 2) void gemm_bf16(
    const u16* __restrict__ Wh, const u16* __restrict__ Wl,
    const u16* __restrict__ Xh, const u16* __restrict__ Xl,
    float* __restrict__ Yf, u16* __restrict__ Ysh, u16* __restrict__ Ysl,
    const float* __restrict__ bias, int M, int N, int thr2, float spscale) {
    const int KD = 384;
    __shared__ __align__(16) u16 Ah[2 * GBUF], Al[2 * GBUF];
    __shared__ __align__(16) u16 Bh[2 * GBUF], Bl[2 * GBUF];
    const int bz = blockIdx.z;
    const size_t xoff = (size_t)bz * KD * N;
    const int m0 = blockIdx.y * 128, n0 = blockIdx.x * 128;
    const int tid = threadIdx.x, lane = tid & 31, wid = tid >> 5;
    const int wm = wid & 3, wn = wid >> 2;
    const bool full3 = (m0 >= thr2);
    float c[2][8][4] = {};

    const int arow = tid >> 1, acol = (tid & 1) * 8;
    const int bro = tid >> 4, bcol = (tid & 15) * 8;   // NN
    const int bn2 = tid >> 1, bk2 = (tid & 1) * 8;     // BT

    auto STAGE = [&](int kc, int buf) {
        size_t ao = (size_t)(m0 + arow) * KD + kc * 16 + acol;
        cpa16(&Ah[buf * GBUF + arow * SST + acol], &Wh[ao], true);
        cpa16(&Al[buf * GBUF + arow * SST + acol], &Wl[ao], true);
        if (!BT) {
            bool v = (n0 + bcol) < N;
            size_t o = xoff + (size_t)(kc * 16 + bro) * N + n0 + bcol;
            cpa16(&Bh[buf * GBUF + bro * BNS + bcol], v ? &Xh[o] : Xh, v);
            cpa16(&Bl[buf * GBUF + bro * BNS + bcol], v ? &Xl[o] : Xl, v);
        } else {
            bool v = (n0 + bn2) < N;
            size_t o = xoff + (size_t)(n0 + bn2) * KD + kc * 16 + bk2;
            cpa16(&Bh[buf * GBUF + bn2 * SST + bk2], v ? &Xh[o] : Xh, v);
            cpa16(&Bl[buf * GBUF + bn2 * SST + bk2], v ? &Xl[o] : Xl, v);
        }
    };

    STAGE(0, 0); CPA_COMMIT;
    const int afr = wm * 32 + (lane & 15);
    const int afc = (lane >> 4) << 3;
    for (int kc = 0; kc < 24; kc++) {
        const int buf = kc & 1;
        CPA_WAIT0;
        __syncthreads();
        if (kc < 23) { STAGE(kc + 1, buf ^ 1); CPA_COMMIT; }
        uint32_t ah[2][4], al[2][4];
        #pragma unroll
        for (int mt = 0; mt < 2; mt++) {
            ldsm4(ah[mt], &Ah[buf * GBUF + (afr + mt * 16) * SST + afc]);
            ldsm4(al[mt], &Al[buf * GBUF + (afr + mt * 16) * SST + afc]);
        }
        #pragma unroll
        for (int p = 0; p < 4; p++) {
            uint32_t bh4[4], bl4[4];
            if (!BT) {
                int r = lane & 15, cN = wn * 64 + p * 16 + afc;
                ldsm4t(bh4, &Bh[buf * GBUF + r * BNS + cN]);
                ldsm4t(bl4, &Bl[buf * GBUF + r * BNS + cN]);
            } else {
                int r = wn * 64 + p * 16 + (lane & 7) + afc;
                int cK = ((lane >> 3) & 1) << 3;
                ldsm4(bh4, &Bh[buf * GBUF + r * SST + cK]);
                ldsm4(bl4, &Bl[buf * GBUF + r * SST + cK]);
            }
            #pragma unroll
            for (int sub = 0; sub < 2; sub++) {
                int nt = 2 * p + sub;
                #pragma unroll
                for (int mt = 0; mt < 2; mt++) {
                    mma_bf16(c[mt][nt], ah[mt], &bh4[2 * sub]);
                    mma_bf16(c[mt][nt], al[mt], &bh4[2 * sub]);
                    if (full3) mma_bf16(c[mt][nt], ah[mt], &bl4[2 * sub]);
                }
            }
        }
        __syncthreads();
    }

    const int g = lane >> 2, tq = lane & 3;
    #pragma unroll
    for (int mt = 0; mt < 2; mt++) {
        int row0 = m0 + wm * 32 + mt * 16 + g;
        int row1 = row0 + 8;
        float bv0 = bias ? bias[row0] : 0.f;
        float bv1 = bias ? bias[row1] : 0.f;
        #pragma unroll
        for (int nt = 0; nt < 8; nt++) {
            int col = n0 + wn * 64 + nt * 8 + 2 * tq;
            if (col < N) {
                float v00 = c[mt][nt][0] + bv0, v01 = c[mt][nt][1] + bv0;
                float v10 = c[mt][nt][2] + bv1, v11 = c[mt][nt][3] + bv1;
                size_t o0 = (size_t)bz * M * N + (size_t)row0 * N + col;
                size_t o1 = (size_t)bz * M * N + (size_t)row1 * N + col;
                if (WF32) {
                    *(float2*)&Yf[o0] = make_float2(v00, v01);
                    *(float2*)&Yf[o1] = make_float2(v10, v11);
                }
                if (WSPLIT) {
                    u16 h0, l0, h1, l1;
                    split1(v00 * spscale, h0, l0); split1(v01 * spscale, h1, l1);
                    *(uint32_t*)&Ysh[o0] = ((uint32_t)h1 << 16) | h0;
                    *(uint32_t*)&Ysl[o0] = ((uint32_t)l1 << 16) | l0;
                    split1(v10 * spscale, h0, l0); split1(v11 * spscale, h1, l1);
                    *(uint32_t*)&Ysh[o1] = ((uint32_t)h1 << 16) | h0;
                    *(uint32_t*)&Ysl[o1] = ((uint32_t)l1 << 16) | l0;
                }
            }
        }
    }
}

// ==================================================================
// Fused flash attention: 64q x 64k tiles, 4 warps, 2-term QK, 3-term PV,
// cp.async double-buffered KV, occ 3 (R8 geometry). Last tile skips dead mmas.
// ==================================================================
#define AS 72
#define KVB (3 * 64 * AS)
__global__ __launch_bounds__(128, 3) void attn_bf16(
    const u16* __restrict__ qh, const u16* __restrict__ ql,
    const u16* __restrict__ kvh, const u16* __restrict__ kvl,
    u16* __restrict__ oh, u16* __restrict__ ol) {
    extern __shared__ __align__(16) u16 smx[];
    u16* Qh = smx;
    u16* Ql = Qh + 64 * AS;
    u16* KV = Ql + 64 * AS;   // buf b: Kh=KV+b*KVB, Vh=+64*AS, Vl=+2*64*AS
    const int qb = blockIdx.x * 64, h = blockIdx.y, b = blockIdx.z;
    const int tid = threadIdx.x, lane = tid & 31, wid = tid >> 5;
    const int g = lane >> 2, tq = lane & 3;
    const size_t qoff = ((size_t)(b * DIM + h * DH)) * HWQ + qb;
    const size_t koff = ((size_t)(b * 2 * DIM + h * DH)) * LO;
    const size_t voff = ((size_t)(b * 2 * DIM + DIM + h * DH)) * LO;

    auto STAGE_KV = [&](int t, int buf) {
        u16* Kh = KV + buf * KVB;
        u16* Vh = Kh + 64 * AS;
        u16* Vl = Vh + 64 * AS;
        for (int i = tid; i < 512; i += 128) {
            int d = i >> 3, c8 = (i & 7) * 8;
            int key = t * 64 + c8;
            bool v = key < LO;
            size_t gk = koff + (size_t)d * LO + key;
            size_t gv = voff + (size_t)d * LO + key;
            cpa16(&Kh[d * AS + c8], v ? &kvh[gk] : kvh, v);
            cpa16(&Vh[d * AS + c8], v ? &kvh[gv] : kvh, v);
            cpa16(&Vl[d * AS + c8], v ? &kvl[gv] : kvl, v);
        }
    };

    // stage Q [q][d]
    for (int i = tid; i < 4096; i += 128) {
        int d = i >> 6, qq = i & 63;
        Qh[qq * AS + d] = qh[qoff + (size_t)d * HWQ + qq];
        Ql[qq * AS + d] = ql[qoff + (size_t)d * HWQ + qq];
    }
    STAGE_KV(0, 0); CPA_COMMIT;
    __syncthreads();
    uint32_t qfh[4][4], qfl[4][4];
    const int afr = wid * 16 + (lane & 15);
    const int afc = (lane >> 4) << 3;
    #pragma unroll
    for (int kc = 0; kc < 4; kc++) {
        ldsm4(qfh[kc], &Qh[afr * AS + kc * 16 + afc]);
        ldsm4(qfl[kc], &Ql[afr * AS + kc * 16 + afc]);
    }

    float o[8][4] = {};
    float mrow0 = -1e30f, mrow1 = -1e30f, lrow0 = 0.f, lrow1 = 0.f;

    for (int t = 0; t < 13; t++) {
        const int buf = t & 1;
        u16* Kh = KV + buf * KVB;
        u16* Vh = Kh + 64 * AS;
        u16* Vl = Vh + 64 * AS;
        CPA_WAIT0;
        __syncthreads();
        if (t < 12) { STAGE_KV(t + 1, buf ^ 1); CPA_COMMIT; }

        const int pmax = (t == 12) ? 1 : 4;   // last tile: only keys 768..783 valid (chunk 0)
        float s[8][4] = {};
        #pragma unroll
        for (int kc = 0; kc < 4; kc++) {
            #pragma unroll
            for (int p = 0; p < 4; p++) {
                if (p >= pmax) break;
                uint32_t bh4[4];
                int r = kc * 16 + (lane & 15), cN = p * 16 + afc;
                ldsm4t(bh4, &Kh[r * AS + cN]);
                #pragma unroll
                for (int sub = 0; sub < 2; sub++) {
                    int nt = 2 * p + sub;
                    mma_bf16(s[nt], qfh[kc], &bh4[2 * sub]);
                    mma_bf16(s[nt], qfl[kc], &bh4[2 * sub]);
                }
            }
        }
        if (t == 12) {
            #pragma unroll
            for (int nt = 0; nt < 8; nt++) {
                int key0 = 768 + nt * 8 + 2 * tq;
                if (key0 >= LO) { s[nt][0] = s[nt][1] = s[nt][2] = s[nt][3] = -1e30f; }
            }
        }
        // online softmax (rows g, g+8)
        float mx0 = -1e30f, mx1 = -1e30f;
        #pragma unroll
        for (int nt = 0; nt < 8; nt++) {
            mx0 = fmaxf(mx0, fmaxf(s[nt][0], s[nt][1]));
            mx1 = fmaxf(mx1, fmaxf(s[nt][2], s[nt][3]));
        }
        mx0 = fmaxf(mx0, __shfl_xor_sync(0xffffffffu, mx0, 1));
        mx0 = fmaxf(mx0, __shfl_xor_sync(0xffffffffu, mx0, 2));
        mx1 = fmaxf(mx1, __shfl_xor_sync(0xffffffffu, mx1, 1));
        mx1 = fmaxf(mx1, __shfl_xor_sync(0xffffffffu, mx1, 2));
        float nm0 = fmaxf(mrow0, mx0), nm1 = fmaxf(mrow1, mx1);
        float corr0 = __expf(mrow0 - nm0), corr1 = __expf(mrow1 - nm1);
        mrow0 = nm0; mrow1 = nm1;
        float ps0 = 0.f, ps1 = 0.f;
        #pragma unroll
        for (int nt = 0; nt < 8; nt++) {
            s[nt][0] = __expf(s[nt][0] - nm0); ps0 += s[nt][0];
            s[nt][1] = __expf(s[nt][1] - nm0); ps0 += s[nt][1];
            s[nt][2] = __expf(s[nt][2] - nm1); ps1 += s[nt][2];
            s[nt][3] = __expf(s[nt][3] - nm1); ps1 += s[nt][3];
        }
        ps0 += __shfl_xor_sync(0xffffffffu, ps0, 1);
        ps0 += __shfl_xor_sync(0xffffffffu, ps0, 2);
        ps1 += __shfl_xor_sync(0xffffffffu, ps1, 1);
        ps1 += __shfl_xor_sync(0xffffffffu, ps1, 2);
        lrow0 = lrow0 * corr0 + ps0;
        lrow1 = lrow1 * corr1 + ps1;
        #pragma unroll
        for (int nt = 0; nt < 8; nt++) {
            o[nt][0] *= corr0; o[nt][1] *= corr0;
            o[nt][2] *= corr1; o[nt][3] *= corr1;
        }
        // P fragments + PV (3-term). Last tile: only key-chunk kc=0 has nonzero p.
        const int kcmax = (t == 12) ? 1 : 4;
        uint32_t ph[4][4], pl[4][4];
        #pragma unroll
        for (int kc = 0; kc < 4; kc++) {
            if (kc >= kcmax) break;
            split_pack(s[2 * kc][0],     s[2 * kc][1],     ph[kc][0], pl[kc][0]);
            split_pack(s[2 * kc][2],     s[2 * kc][3],     ph[kc][1], pl[kc][1]);
            split_pack(s[2 * kc + 1][0], s[2 * kc + 1][1], ph[kc][2], pl[kc][2]);
            split_pack(s[2 * kc + 1][2], s[2 * kc + 1][3], ph[kc][3], pl[kc][3]);
        }
        #pragma unroll
        for (int kc = 0; kc < 4; kc++) {
            if (kc >= kcmax) break;
            #pragma unroll
            for (int p = 0; p < 4; p++) {
                uint32_t vh4[4], vl4[4];
                int vr = p * 16 + (lane & 7) + afc;
                int vc = kc * 16 + (((lane >> 3) & 1) << 3);
                ldsm4(vh4, &Vh[vr * AS + vc]);
                ldsm4(vl4, &Vl[vr * AS + vc]);
                #pragma unroll
                for (int sub = 0; sub < 2; sub++) {
                    int nt = 2 * p + sub;
                    mma_bf16(o[nt], ph[kc], &vh4[2 * sub]);
                    mma_bf16(o[nt], pl[kc], &vh4[2 * sub]);
                    mma_bf16(o[nt], ph[kc], &vl4[2 * sub]);
                }
            }
        }
        __syncthreads();
    }
    float inv0 = 1.f / lrow0, inv1 = 1.f / lrow1;
    size_t base = (size_t)b * HWQ + qb;
    int rlo = wid * 16 + g, rhi = rlo + 8;
    #pragma unroll
    for (int nt = 0; nt < 8; nt++) {
        int d = h * DH + nt * 8 + 2 * tq;
        u16 h0, l0, h1, l1;
        split1(o[nt][0] * inv0, h0, l0); split1(o[nt][1] * inv0, h1, l1);
        *(uint32_t*)&oh[(base + rlo) * DIM + d] = ((uint32_t)h1 << 16) | h0;
        *(uint32_t*)&ol[(base + rlo) * DIM + d] = ((uint32_t)l1 << 16) | l0;
        split1(o[nt][2] * inv1, h0, l0); split1(o[nt][3] * inv1, h1, l1);
        *(uint32_t*)&oh[(base + rhi) * DIM + d] = ((uint32_t)h1 << 16) | h0;
        *(uint32_t*)&ol[(base + rhi) * DIM + d] = ((uint32_t)l1 << 16) | l0;
    }
}

// ---------------- depthwise 5x5 s2 + bias + BN + exact GELU ----------------
__global__ void dw_bn_gelu_kernel(const float* __restrict__ q,
                                  const float* __restrict__ dw_w, const float* __restrict__ dw_b,
                                  const float* __restrict__ bn_w, const float* __restrict__ bn_b,
                                  const float* __restrict__ bn_mean, const float* __restrict__ bn_var,
                                  float* __restrict__ off) {
    int idx = blockIdx.x * blockDim.x + threadIdx.x;
    const int TOT = BSZ * GRP * NGD * LO;
    if (idx >= TOT) return;
    int pix = idx % LO;
    int c   = (idx / LO) % NGD;
    int n   = idx / (LO * NGD);
    int oy = pix / WO, ox = pix % WO;
    int b = n / GRP, g = n % GRP;
    const float* plane = q + ((size_t)(b * DIM + g * NGD + c)) * HWQ;
    const float* wk = dw_w + c * 25;
    float s = 0.f;
    #pragma unroll
    for (int ky = 0; ky < 5; ky++) {
        int iy = oy * 2 + ky - 2;
        if (iy < 0 || iy >= HH) continue;
        #pragma unroll
        for (int kx = 0; kx < 5; kx++) {
            int ix = ox * 2 + kx - 2;
            if (ix >= 0 && ix < WW) s = fmaf(plane[iy * WW + ix], wk[ky * 5 + kx], s);
        }
    }
    s += dw_b[c];
    s = (s - bn_mean[c]) * (bn_w[c] * rsqrtf(bn_var[c] + 1e-6f)) + bn_b[c];
    s = 0.5f * s * (1.0f + erff(s * 0.70710678118654752f));
    off[idx] = s;
}

// ---------------- pointwise 128->3 + offset/grid math ----------------
__global__ void pw_grid_kernel(const float* __restrict__ off, const float* __restrict__ pw_w,
                               float4* __restrict__ grid4) {
    int idx = blockIdx.x * blockDim.x + threadIdx.x;
    const int TOT = BSZ * GRP * LO;
    if (idx >= TOT) return;
    int n = idx / LO, pix = idx % LO;
    const float* base = off + (size_t)n * NGD * LO + pix;
    float o0 = 0.f, o1 = 0.f, o2 = 0.f;
    #pragma unroll 4
    for (int c = 0; c < NGD; c++) {
        float v = base[(size_t)c * LO];
        o0 = fmaf(v, pw_w[c], o0);
        o1 = fmaf(v, pw_w[NGD + c], o1);
        o2 = fmaf(v, pw_w[2 * NGD + c], o2);
    }
    int oy = pix / WO, ox = pix % WO;
    float ry = ((0.5f + (float)oy) / (float)HO) * 2.f - 1.f;
    float rx = ((0.5f + (float)ox) / (float)WO) * 2.f - 1.f;
    float posy = tanhf(o0) * (2.0f / (float)HO) + ry;
    float posx = tanhf(o1) * (2.0f / (float)WO) + rx;
    float gx = (posx + 1.f) * 0.5f * (float)(WW - 1);
    float gy = (posy + 1.f) * 0.5f * (float)(HH - 1);
    float sig = 1.f / (1.f + expf(-o2));
    float mod = 1.f / (1.f + expf(-sig));
    grid4[idx] = make_float4(gx, gy, mod, 0.f);
}

// ---------------- bilinear grid sample * modulation -> split bf16 ----------------
__global__ void sample_kernel(const float* __restrict__ x, const float4* __restrict__ grid4,
                              u16* __restrict__ xsh, u16* __restrict__ xsl) {
    int nc = blockIdx.x;
    int pix = blockIdx.y * blockDim.x + threadIdx.x;
    if (pix >= LO) return;
    int c = nc & (NGD - 1), n = nc >> 7;
    int b = n / GRP, g = n % GRP;
    float4 gq = grid4[(size_t)n * LO + pix];
    float gx = gq.x, gy = gq.y, mod = gq.z;
    float x0f = floorf(gx), y0f = floorf(gy);
    float x1f = x0f + 1.f, y1f = y0f + 1.f;
    const float* plane = x + ((size_t)(b * DIM + g * NGD + c)) * HWQ;

    float t00 = 0.f, t01 = 0.f, t10 = 0.f, t11 = 0.f;
    bool vx0 = (x0f >= 0.f) && (x0f <= (float)(WW - 1));
    bool vx1 = (x1f >= 0.f) && (x1f <= (float)(WW - 1));
    bool vy0 = (y0f >= 0.f) && (y0f <= (float)(HH - 1));
    bool vy1 = (y1f >= 0.f) && (y1f <= (float)(HH - 1));
    int xi0 = (int)fminf(fmaxf(x0f, 0.f), (float)(WW - 1));
    int xi1 = (int)fminf(fmaxf(x1f, 0.f), (float)(WW - 1));
    int yi0 = (int)fminf(fmaxf(y0f, 0.f), (float)(HH - 1));
    int yi1 = (int)fminf(fmaxf(y1f, 0.f), (float)(HH - 1));
    if (vy0 && vx0) t00 = plane[yi0 * WW + xi0];
    if (vy1 && vx0) t10 = plane[yi1 * WW + xi0];
    if (vy0 && vx1) t01 = plane[yi0 * WW + xi1];
    if (vy1 && vx1) t11 = plane[yi1 * WW + xi1];

    float v = t00 * (x1f - gx) * (y1f - gy)
            + t10 * (x1f - gx) * (gy - y0f)
            + t01 * (gx - x0f) * (y1f - gy)
            + t11 * (gx - x0f) * (gy - y0f);
    v *= mod;
    u16 hh, ll; split1(v, hh, ll);
    size_t o = ((size_t)(b * DIM + g * NGD + c)) * LO + pix;
    xsh[o] = hh; xsl[o] = ll;
}

// ---------------- launch ----------------
extern "C" void kernel_launch(void* const* d_in, const int* in_sizes, int n_in,
                              void* d_out, int out_size) {
    const float* x      = (const float*)d_in[0];
    const float* q_w    = (const float*)d_in[1];
    const float* kv_w   = (const float*)d_in[2];
    const float* proj_w = (const float*)d_in[3];
    const float* proj_b = (const float*)d_in[4];
    const float* dw_w   = (const float*)d_in[5];
    const float* dw_b   = (const float*)d_in[6];
    const float* bn_w   = (const float*)d_in[7];
    const float* bn_b   = (const float*)d_in[8];
    const float* bn_mean= (const float*)d_in[9];
    const float* bn_var = (const float*)d_in[10];
    const float* pw_w   = (const float*)d_in[11];
    float* out = (float*)d_out;

    float *q, *off; float4* grid;
    u16 *qh, *ql, *xh, *xl, *wqh, *wql, *wkh, *wkl, *wph, *wpl;
    u16 *xsh, *xsl, *kvh, *kvl, *ah, *al;
    cudaGetSymbolAddress((void**)&q,    d_q);
    cudaGetSymbolAddress((void**)&off,  d_off);
    cudaGetSymbolAddress((void**)&grid, d_grid);
    cudaGetSymbolAddress((void**)&qh,   d_qh);
    cudaGetSymbolAddress((void**)&ql,   d_ql);
    cudaGetSymbolAddress((void**)&xh,   d_xh);
    cudaGetSymbolAddress((void**)&xl,   d_xl);
    cudaGetSymbolAddress((void**)&wqh,  d_wqh);
    cudaGetSymbolAddress((void**)&wql,  d_wql);
    cudaGetSymbolAddress((void**)&wkh,  d_wkh);
    cudaGetSymbolAddress((void**)&wkl,  d_wkl);
    cudaGetSymbolAddress((void**)&wph,  d_wph);
    cudaGetSymbolAddress((void**)&wpl,  d_wpl);
    cudaGetSymbolAddress((void**)&xsh,  d_xsh);
    cudaGetSymbolAddress((void**)&xsl,  d_xsl);
    cudaGetSymbolAddress((void**)&kvh,  d_kvh);
    cudaGetSymbolAddress((void**)&kvl,  d_kvl);
    cudaGetSymbolAddress((void**)&ah,   d_ah);
    cudaGetSymbolAddress((void**)&al,   d_al);

    // pre-split x and weights
    {
        int n4 = BSZ * DIM * HWQ / 4;
        split_kernel<<<(n4 + 255) / 256, 256>>>(x, xh, xl, n4);
        int w4 = DIM * DIM / 4;
        split_kernel<<<(w4 + 255) / 256, 256>>>(q_w, wqh, wql, w4);
        split_kernel<<<(2 * w4 + 255) / 256, 256>>>(kv_w, wkh, wkl, 2 * w4);
        split_kernel<<<(w4 + 255) / 256, 256>>>(proj_w, wph, wpl, w4);
    }
    // K1: q = q_w @ x  -> f32 + split (Q split pre-scaled by SCALE)
    {
        dim3 g1((HWQ + 127) / 128, DIM / 128, BSZ);
        gemm_bf16<false, true, true><<<g1, 256>>>(wqh, wql, xh, xl, q, qh, ql,
                                                  nullptr, DIM, HWQ, 0, SCALE);
    }
    // K2: depthwise conv + bias + BN + gelu
    {
        int tot = BSZ * GRP * NGD * LO;
        dw_bn_gelu_kernel<<<(tot + 255) / 256, 256>>>(q, dw_w, dw_b, bn_w, bn_b,
                                                      bn_mean, bn_var, off);
    }
    // K3a: pointwise + grid
    {
        int tot = BSZ * GRP * LO;
        pw_grid_kernel<<<(tot + 255) / 256, 256>>>(off, pw_w, grid);
    }
    // K3b: bilinear sampling -> xs split
    {
        dim3 g((BSZ * GRP * NGD), (LO + 255) / 256);
        sample_kernel<<<g, 256>>>(x, grid, xsh, xsl);
    }
    // K4: kv = kv_w @ xs -> split only (k-half m0<384 uses 2-term)
    {
        dim3 g((LO + 127) / 128, (2 * DIM) / 128, BSZ);
        gemm_bf16<false, false, true><<<g, 256>>>(wkh, wkl, xsh, xsl, nullptr,
                                                  kvh, kvl, nullptr, 2 * DIM, LO, DIM, 1.0f);
    }
    // K5: fused attention (64q tiles, occ 3, last-tile skip) -> attn split
    {
        dim3 g(HWQ / 64, NH, BSZ);
        size_t smem = (size_t)(2 * 64 * AS + 2 * KVB) * sizeof(u16);  // 73728 B
        cudaFuncSetAttribute(attn_bf16, cudaFuncAttributeMaxDynamicSharedMemorySize, (int)smem);
        attn_bf16<<<g, 128, smem>>>(qh, ql, kvh, kvl, ah, al);
    }
    // K6: out = proj_w @ attn^T + proj_b  (3-term)
    {
        dim3 g1((HWQ + 127) / 128, DIM / 128, BSZ);
        gemm_bf16<true, true, false><<<g1, 256>>>(wph, wpl, ah, al, out,
                                                  nullptr, nullptr, proj_b, DIM, HWQ, 0, 1.0f);
    }
}

// round 13
// speedup vs baseline: 1.1578x; 1.0876x over previous
#include <cuda_runtime.h>
#include <cuda_bf16.h>
#include <math.h>
#include <stdint.h>

// ---------------- problem constants ----------------
#define BSZ   8
#define DIM   384
#define HH    56
#define WW    56
#define HWQ   3136
#define NH    6
#define DH    64
#define GRP   3
#define NGD   128
#define HO    28
#define WO    28
#define LO    784
#define SCALE 0.125f

typedef unsigned short u16;

// ---------------- scratch (device globals, no allocs) ----------------
__device__ float  d_q  [(size_t)BSZ * DIM * HWQ];
__device__ u16    d_qh [(size_t)BSZ * DIM * HWQ];   // pre-scaled by SCALE
__device__ u16    d_ql [(size_t)BSZ * DIM * HWQ];
__device__ u16    d_xh [(size_t)BSZ * DIM * HWQ];
__device__ u16    d_xl [(size_t)BSZ * DIM * HWQ];
__device__ u16    d_wqh[DIM * DIM],     d_wql[DIM * DIM];
__device__ u16    d_wkh[2 * DIM * DIM], d_wkl[2 * DIM * DIM];
__device__ u16    d_wph[DIM * DIM],     d_wpl[DIM * DIM];
__device__ float  d_off [(size_t)BSZ * GRP * NGD * LO];
__device__ float4 d_grid[(size_t)BSZ * GRP * LO];
__device__ u16    d_xsh[(size_t)BSZ * DIM * LO],     d_xsl[(size_t)BSZ * DIM * LO];
__device__ u16    d_kvh[(size_t)BSZ * 2 * DIM * LO], d_kvl[(size_t)BSZ * 2 * DIM * LO];
__device__ u16    d_ah [(size_t)BSZ * HWQ * DIM],    d_al [(size_t)BSZ * HWQ * DIM];

// ---------------- helpers ----------------
__device__ __forceinline__ void split1(float x, u16& h, u16& l) {
    __nv_bfloat16 bh = __float2bfloat16(x);
    float r = x - __bfloat162float(bh);
    __nv_bfloat16 bl = __float2bfloat16(r);
    h = __bfloat16_as_ushort(bh);
    l = __bfloat16_as_ushort(bl);
}
__device__ __forceinline__ void split_pack(float x, float y, uint32_t& ph, uint32_t& pl) {
    u16 xh, xl, yh, yl;
    split1(x, xh, xl); split1(y, yh, yl);
    ph = ((uint32_t)yh << 16) | xh;
    pl = ((uint32_t)yl << 16) | xl;
}
__device__ __forceinline__ void mma_bf16(float* c, const uint32_t* a, const uint32_t* b) {
    asm volatile(
        "mma.sync.aligned.m16n8k16.row.col.f32.bf16.bf16.f32 "
        "{%0,%1,%2,%3}, {%4,%5,%6,%7}, {%8,%9}, {%0,%1,%2,%3};\n"
        : "+f"(c[0]), "+f"(c[1]), "+f"(c[2]), "+f"(c[3])
        : "r"(a[0]), "r"(a[1]), "r"(a[2]), "r"(a[3]), "r"(b[0]), "r"(b[1]));
}
__device__ __forceinline__ void ldsm4(uint32_t* r, const u16* p) {
    uint32_t a = (uint32_t)__cvta_generic_to_shared(p);
    asm volatile("ldmatrix.sync.aligned.m8n8.x4.shared.b16 {%0,%1,%2,%3}, [%4];"
                 : "=r"(r[0]), "=r"(r[1]), "=r"(r[2]), "=r"(r[3]) : "r"(a));
}
__device__ __forceinline__ void ldsm4t(uint32_t* r, const u16* p) {
    uint32_t a = (uint32_t)__cvta_generic_to_shared(p);
    asm volatile("ldmatrix.sync.aligned.m8n8.x4.trans.shared.b16 {%0,%1,%2,%3}, [%4];"
                 : "=r"(r[0]), "=r"(r[1]), "=r"(r[2]), "=r"(r[3]) : "r"(a));
}
// cp.async 16B with zero-fill when pred false
__device__ __forceinline__ void cpa16(u16* dst, const u16* src, bool pred) {
    uint32_t d = (uint32_t)__cvta_generic_to_shared(dst);
    int sz = pred ? 16 : 0;
    asm volatile("cp.async.cg.shared.global [%0], [%1], 16, %2;"
                 :: "r"(d), "l"(src), "r"(sz));
}
#define CPA_COMMIT asm volatile("cp.async.commit_group;" ::: "memory")
#define CPA_WAIT0  asm volatile("cp.async.wait_group 0;" ::: "memory")

// ---------------- f32 -> (hi,lo) bf16 split ----------------
__global__ void split_kernel(const float* __restrict__ src, u16* __restrict__ h,
                             u16* __restrict__ l, int n4) {
    int i = blockIdx.x * blockDim.x + threadIdx.x;
    if (i >= n4) return;
    float4 v = ((const float4*)src)[i];
    ushort4 hh, ll;
    split1(v.x, hh.x, ll.x); split1(v.y, hh.y, ll.y);
    split1(v.z, hh.z, ll.z); split1(v.w, hh.w, ll.w);
    ((ushort4*)h)[i] = hh; ((ushort4*)l)[i] = ll;
}

// ==================================================================
// GEMM: Y[b] = W(MxK=384) @ X[b](384xN), pre-split bf16 operands,
// cp.async double-buffered. Rows m0<thr2 use 2-term split.
// ==================================================================
#define SST 24
#define BNS 136
#define GBUF (128 * SST)
template<bool BT, bool WF32, bool WSPLIT>
__global__ __launch_bounds__(256, 2) void gemm_bf16(
    const u16* __restrict__ Wh, const u16* __restrict__ Wl,
    const u16* __restrict__ Xh, const u16* __restrict__ Xl,
    float* __restrict__ Yf, u16* __restrict__ Ysh, u16* __restrict__ Ysl,
    const float* __restrict__ bias, int M, int N, int thr2, float spscale) {
    const int KD = 384;
    __shared__ __align__(16) u16 Ah[2 * GBUF], Al[2 * GBUF];
    __shared__ __align__(16) u16 Bh[2 * GBUF], Bl[2 * GBUF];
    const int bz = blockIdx.z;
    const size_t xoff = (size_t)bz * KD * N;
    const int m0 = blockIdx.y * 128, n0 = blockIdx.x * 128;
    const int tid = threadIdx.x, lane = tid & 31, wid = tid >> 5;
    const int wm = wid & 3, wn = wid >> 2;
    const bool full3 = (m0 >= thr2);
    float c[2][8][4] = {};

    const int arow = tid >> 1, acol = (tid & 1) * 8;
    const int bro = tid >> 4, bcol = (tid & 15) * 8;   // NN
    const int bn2 = tid >> 1, bk2 = (tid & 1) * 8;     // BT

    auto STAGE = [&](int kc, int buf) {
        size_t ao = (size_t)(m0 + arow) * KD + kc * 16 + acol;
        cpa16(&Ah[buf * GBUF + arow * SST + acol], &Wh[ao], true);
        cpa16(&Al[buf * GBUF + arow * SST + acol], &Wl[ao], true);
        if (!BT) {
            bool v = (n0 + bcol) < N;
            size_t o = xoff + (size_t)(kc * 16 + bro) * N + n0 + bcol;
            cpa16(&Bh[buf * GBUF + bro * BNS + bcol], v ? &Xh[o] : Xh, v);
            cpa16(&Bl[buf * GBUF + bro * BNS + bcol], v ? &Xl[o] : Xl, v);
        } else {
            bool v = (n0 + bn2) < N;
            size_t o = xoff + (size_t)(n0 + bn2) * KD + kc * 16 + bk2;
            cpa16(&Bh[buf * GBUF + bn2 * SST + bk2], v ? &Xh[o] : Xh, v);
            cpa16(&Bl[buf * GBUF + bn2 * SST + bk2], v ? &Xl[o] : Xl, v);
        }
    };

    STAGE(0, 0); CPA_COMMIT;
    const int afr = wm * 32 + (lane & 15);
    const int afc = (lane >> 4) << 3;
    for (int kc = 0; kc < 24; kc++) {
        const int buf = kc & 1;
        CPA_WAIT0;
        __syncthreads();
        if (kc < 23) { STAGE(kc + 1, buf ^ 1); CPA_COMMIT; }
        uint32_t ah[2][4], al[2][4];
        #pragma unroll
        for (int mt = 0; mt < 2; mt++) {
            ldsm4(ah[mt], &Ah[buf * GBUF + (afr + mt * 16) * SST + afc]);
            ldsm4(al[mt], &Al[buf * GBUF + (afr + mt * 16) * SST + afc]);
        }
        #pragma unroll
        for (int p = 0; p < 4; p++) {
            uint32_t bh4[4], bl4[4];
            if (!BT) {
                int r = lane & 15, cN = wn * 64 + p * 16 + afc;
                ldsm4t(bh4, &Bh[buf * GBUF + r * BNS + cN]);
                ldsm4t(bl4, &Bl[buf * GBUF + r * BNS + cN]);
            } else {
                int r = wn * 64 + p * 16 + (lane & 7) + afc;
                int cK = ((lane >> 3) & 1) << 3;
                ldsm4(bh4, &Bh[buf * GBUF + r * SST + cK]);
                ldsm4(bl4, &Bl[buf * GBUF + r * SST + cK]);
            }
            #pragma unroll
            for (int sub = 0; sub < 2; sub++) {
                int nt = 2 * p + sub;
                #pragma unroll
                for (int mt = 0; mt < 2; mt++) {
                    mma_bf16(c[mt][nt], ah[mt], &bh4[2 * sub]);
                    mma_bf16(c[mt][nt], al[mt], &bh4[2 * sub]);
                    if (full3) mma_bf16(c[mt][nt], ah[mt], &bl4[2 * sub]);
                }
            }
        }
        __syncthreads();
    }

    const int g = lane >> 2, tq = lane & 3;
    #pragma unroll
    for (int mt = 0; mt < 2; mt++) {
        int row0 = m0 + wm * 32 + mt * 16 + g;
        int row1 = row0 + 8;
        float bv0 = bias ? bias[row0] : 0.f;
        float bv1 = bias ? bias[row1] : 0.f;
        #pragma unroll
        for (int nt = 0; nt < 8; nt++) {
            int col = n0 + wn * 64 + nt * 8 + 2 * tq;
            if (col < N) {
                float v00 = c[mt][nt][0] + bv0, v01 = c[mt][nt][1] + bv0;
                float v10 = c[mt][nt][2] + bv1, v11 = c[mt][nt][3] + bv1;
                size_t o0 = (size_t)bz * M * N + (size_t)row0 * N + col;
                size_t o1 = (size_t)bz * M * N + (size_t)row1 * N + col;
                if (WF32) {
                    *(float2*)&Yf[o0] = make_float2(v00, v01);
                    *(float2*)&Yf[o1] = make_float2(v10, v11);
                }
                if (WSPLIT) {
                    u16 h0, l0, h1, l1;
                    split1(v00 * spscale, h0, l0); split1(v01 * spscale, h1, l1);
                    *(uint32_t*)&Ysh[o0] = ((uint32_t)h1 << 16) | h0;
                    *(uint32_t*)&Ysl[o0] = ((uint32_t)l1 << 16) | l0;
                    split1(v10 * spscale, h0, l0); split1(v11 * spscale, h1, l1);
                    *(uint32_t*)&Ysh[o1] = ((uint32_t)h1 << 16) | h0;
                    *(uint32_t*)&Ysl[o1] = ((uint32_t)l1 << 16) | l0;
                }
            }
        }
    }
}

// ==================================================================
// Fused flash attention: 64q x 64k tiles, 4 warps, 2-term QK, 3-term PV,
// cp.async double-buffered KV, occ 3. Last tile is PEELED with static
// reduced bounds (PMAX=1/KCMAX=1) so the mainloop stays fully unrolled.
// ==================================================================
#define AS 72
#define KVB (3 * 64 * AS)

// tile body macro: TT = tile index expr, PMAXV/KCMAXV literals, LASTV literal
#define ATTN_TILE(TT, PMAXV, KCMAXV, LASTV)                                         \
{                                                                                   \
    const int buf_ = (TT) & 1;                                                      \
    u16* Kh = KV + buf_ * KVB;                                                      \
    u16* Vh = Kh + 64 * AS;                                                         \
    u16* Vl = Vh + 64 * AS;                                                         \
    CPA_WAIT0;                                                                      \
    __syncthreads();                                                                \
    if (!(LASTV)) { STAGE_KV((TT) + 1, buf_ ^ 1); CPA_COMMIT; }                     \
    float s[8][4] = {};                                                             \
    _Pragma("unroll")                                                               \
    for (int kc = 0; kc < 4; kc++) {                                                \
        _Pragma("unroll")                                                           \
        for (int p = 0; p < (PMAXV); p++) {                                         \
            uint32_t bh4[4];                                                        \
            int r = kc * 16 + (lane & 15), cN = p * 16 + afc;                       \
            ldsm4t(bh4, &Kh[r * AS + cN]);                                          \
            _Pragma("unroll")                                                       \
            for (int sub = 0; sub < 2; sub++) {                                     \
                int nt = 2 * p + sub;                                               \
                mma_bf16(s[nt], qfh[kc], &bh4[2 * sub]);                            \
                mma_bf16(s[nt], qfl[kc], &bh4[2 * sub]);                            \
            }                                                                       \
        }                                                                           \
    }                                                                               \
    if (LASTV) {                                                                    \
        _Pragma("unroll")                                                           \
        for (int nt = 0; nt < 8; nt++) {                                            \
            int key0 = 768 + nt * 8 + 2 * tq;                                       \
            if (key0 >= LO) { s[nt][0] = s[nt][1] = s[nt][2] = s[nt][3] = -1e30f; } \
        }                                                                           \
    }                                                                               \
    float mx0 = -1e30f, mx1 = -1e30f;                                               \
    _Pragma("unroll")                                                               \
    for (int nt = 0; nt < 8; nt++) {                                                \
        mx0 = fmaxf(mx0, fmaxf(s[nt][0], s[nt][1]));                                \
        mx1 = fmaxf(mx1, fmaxf(s[nt][2], s[nt][3]));                                \
    }                                                                               \
    mx0 = fmaxf(mx0, __shfl_xor_sync(0xffffffffu, mx0, 1));                         \
    mx0 = fmaxf(mx0, __shfl_xor_sync(0xffffffffu, mx0, 2));                         \
    mx1 = fmaxf(mx1, __shfl_xor_sync(0xffffffffu, mx1, 1));                         \
    mx1 = fmaxf(mx1, __shfl_xor_sync(0xffffffffu, mx1, 2));                         \
    float nm0 = fmaxf(mrow0, mx0), nm1 = fmaxf(mrow1, mx1);                         \
    float corr0 = __expf(mrow0 - nm0), corr1 = __expf(mrow1 - nm1);                 \
    mrow0 = nm0; mrow1 = nm1;                                                       \
    float ps0 = 0.f, ps1 = 0.f;                                                     \
    _Pragma("unroll")                                                               \
    for (int nt = 0; nt < 8; nt++) {                                                \
        s[nt][0] = __expf(s[nt][0] - nm0); ps0 += s[nt][0];                         \
        s[nt][1] = __expf(s[nt][1] - nm0); ps0 += s[nt][1];                         \
        s[nt][2] = __expf(s[nt][2] - nm1); ps1 += s[nt][2];                         \
        s[nt][3] = __expf(s[nt][3] - nm1); ps1 += s[nt][3];                         \
    }                                                                               \
    ps0 += __shfl_xor_sync(0xffffffffu, ps0, 1);                                    \
    ps0 += __shfl_xor_sync(0xffffffffu, ps0, 2);                                    \
    ps1 += __shfl_xor_sync(0xffffffffu, ps1, 1);                                    \
    ps1 += __shfl_xor_sync(0xffffffffu, ps1, 2);                                    \
    lrow0 = lrow0 * corr0 + ps0;                                                    \
    lrow1 = lrow1 * corr1 + ps1;                                                    \
    _Pragma("unroll")                                                               \
    for (int nt = 0; nt < 8; nt++) {                                                \
        o[nt][0] *= corr0; o[nt][1] *= corr0;                                       \
        o[nt][2] *= corr1; o[nt][3] *= corr1;                                       \
    }                                                                               \
    uint32_t ph[KCMAXV][4], pl[KCMAXV][4];                                          \
    _Pragma("unroll")                                                               \
    for (int kc = 0; kc < (KCMAXV); kc++) {                                         \
        split_pack(s[2 * kc][0],     s[2 * kc][1],     ph[kc][0], pl[kc][0]);       \
        split_pack(s[2 * kc][2],     s[2 * kc][3],     ph[kc][1], pl[kc][1]);       \
        split_pack(s[2 * kc + 1][0], s[2 * kc + 1][1], ph[kc][2], pl[kc][2]);       \
        split_pack(s[2 * kc + 1][2], s[2 * kc + 1][3], ph[kc][3], pl[kc][3]);       \
    }                                                                               \
    _Pragma("unroll")                                                               \
    for (int kc = 0; kc < (KCMAXV); kc++) {                                         \
        _Pragma("unroll")                                                           \
        for (int p = 0; p < 4; p++) {                                               \
            uint32_t vh4[4], vl4[4];                                                \
            int vr = p * 16 + (lane & 7) + afc;                                     \
            int vc = kc * 16 + (((lane >> 3) & 1) << 3);                            \
            ldsm4(vh4, &Vh[vr * AS + vc]);                                          \
            ldsm4(vl4, &Vl[vr * AS + vc]);                                          \
            _Pragma("unroll")                                                       \
            for (int sub = 0; sub < 2; sub++) {                                     \
                int nt = 2 * p + sub;                                               \
                mma_bf16(o[nt], ph[kc], &vh4[2 * sub]);                             \
                mma_bf16(o[nt], pl[kc], &vh4[2 * sub]);                             \
                mma_bf16(o[nt], ph[kc], &vl4[2 * sub]);                             \
            }                                                                       \
        }                                                                           \
    }                                                                               \
    __syncthreads();                                                                \
}

__global__ __launch_bounds__(128, 3) void attn_bf16(
    const u16* __restrict__ qh, const u16* __restrict__ ql,
    const u16* __restrict__ kvh, const u16* __restrict__ kvl,
    u16* __restrict__ oh, u16* __restrict__ ol) {
    extern __shared__ __align__(16) u16 smx[];
    u16* Qh = smx;
    u16* Ql = Qh + 64 * AS;
    u16* KV = Ql + 64 * AS;   // buf b: Kh=KV+b*KVB, Vh=+64*AS, Vl=+2*64*AS
    const int qb = blockIdx.x * 64, h = blockIdx.y, b = blockIdx.z;
    const int tid = threadIdx.x, lane = tid & 31, wid = tid >> 5;
    const int g = lane >> 2, tq = lane & 3;
    const size_t qoff = ((size_t)(b * DIM + h * DH)) * HWQ + qb;
    const size_t koff = ((size_t)(b * 2 * DIM + h * DH)) * LO;
    const size_t voff = ((size_t)(b * 2 * DIM + DIM + h * DH)) * LO;

    auto STAGE_KV = [&](int t, int buf) {
        u16* Kh = KV + buf * KVB;
        u16* Vh = Kh + 64 * AS;
        u16* Vl = Vh + 64 * AS;
        for (int i = tid; i < 512; i += 128) {
            int d = i >> 3, c8 = (i & 7) * 8;
            int key = t * 64 + c8;
            bool v = key < LO;
            size_t gk = koff + (size_t)d * LO + key;
            size_t gv = voff + (size_t)d * LO + key;
            cpa16(&Kh[d * AS + c8], v ? &kvh[gk] : kvh, v);
            cpa16(&Vh[d * AS + c8], v ? &kvh[gv] : kvh, v);
            cpa16(&Vl[d * AS + c8], v ? &kvl[gv] : kvl, v);
        }
    };

    // stage Q [q][d]
    for (int i = tid; i < 4096; i += 128) {
        int d = i >> 6, qq = i & 63;
        Qh[qq * AS + d] = qh[qoff + (size_t)d * HWQ + qq];
        Ql[qq * AS + d] = ql[qoff + (size_t)d * HWQ + qq];
    }
    STAGE_KV(0, 0); CPA_COMMIT;
    __syncthreads();
    uint32_t qfh[4][4], qfl[4][4];
    const int afr = wid * 16 + (lane & 15);
    const int afc = (lane >> 4) << 3;
    #pragma unroll
    for (int kc = 0; kc < 4; kc++) {
        ldsm4(qfh[kc], &Qh[afr * AS + kc * 16 + afc]);
        ldsm4(qfl[kc], &Ql[afr * AS + kc * 16 + afc]);
    }

    float o[8][4] = {};
    float mrow0 = -1e30f, mrow1 = -1e30f, lrow0 = 0.f, lrow1 = 0.f;

    // main tiles 0..11 (full static body), then peeled last tile (static reduced)
    for (int t = 0; t < 12; t++) {
        ATTN_TILE(t, 4, 4, false)
    }
    ATTN_TILE(12, 1, 1, true)

    float inv0 = 1.f / lrow0, inv1 = 1.f / lrow1;
    size_t base = (size_t)b * HWQ + qb;
    int rlo = wid * 16 + g, rhi = rlo + 8;
    #pragma unroll
    for (int nt = 0; nt < 8; nt++) {
        int d = h * DH + nt * 8 + 2 * tq;
        u16 h0, l0, h1, l1;
        split1(o[nt][0] * inv0, h0, l0); split1(o[nt][1] * inv0, h1, l1);
        *(uint32_t*)&oh[(base + rlo) * DIM + d] = ((uint32_t)h1 << 16) | h0;
        *(uint32_t*)&ol[(base + rlo) * DIM + d] = ((uint32_t)l1 << 16) | l0;
        split1(o[nt][2] * inv1, h0, l0); split1(o[nt][3] * inv1, h1, l1);
        *(uint32_t*)&oh[(base + rhi) * DIM + d] = ((uint32_t)h1 << 16) | h0;
        *(uint32_t*)&ol[(base + rhi) * DIM + d] = ((uint32_t)l1 << 16) | l0;
    }
}

// ---------------- depthwise 5x5 s2 + bias + BN + exact GELU ----------------
__global__ void dw_bn_gelu_kernel(const float* __restrict__ q,
                                  const float* __restrict__ dw_w, const float* __restrict__ dw_b,
                                  const float* __restrict__ bn_w, const float* __restrict__ bn_b,
                                  const float* __restrict__ bn_mean, const float* __restrict__ bn_var,
                                  float* __restrict__ off) {
    int idx = blockIdx.x * blockDim.x + threadIdx.x;
    const int TOT = BSZ * GRP * NGD * LO;
    if (idx >= TOT) return;
    int pix = idx % LO;
    int c   = (idx / LO) % NGD;
    int n   = idx / (LO * NGD);
    int oy = pix / WO, ox = pix % WO;
    int b = n / GRP, g = n % GRP;
    const float* plane = q + ((size_t)(b * DIM + g * NGD + c)) * HWQ;
    const float* wk = dw_w + c * 25;
    float s = 0.f;
    #pragma unroll
    for (int ky = 0; ky < 5; ky++) {
        int iy = oy * 2 + ky - 2;
        if (iy < 0 || iy >= HH) continue;
        #pragma unroll
        for (int kx = 0; kx < 5; kx++) {
            int ix = ox * 2 + kx - 2;
            if (ix >= 0 && ix < WW) s = fmaf(plane[iy * WW + ix], wk[ky * 5 + kx], s);
        }
    }
    s += dw_b[c];
    s = (s - bn_mean[c]) * (bn_w[c] * rsqrtf(bn_var[c] + 1e-6f)) + bn_b[c];
    s = 0.5f * s * (1.0f + erff(s * 0.70710678118654752f));
    off[idx] = s;
}

// ---------------- pointwise 128->3 + offset/grid math ----------------
__global__ void pw_grid_kernel(const float* __restrict__ off, const float* __restrict__ pw_w,
                               float4* __restrict__ grid4) {
    int idx = blockIdx.x * blockDim.x + threadIdx.x;
    const int TOT = BSZ * GRP * LO;
    if (idx >= TOT) return;
    int n = idx / LO, pix = idx % LO;
    const float* base = off + (size_t)n * NGD * LO + pix;
    float o0 = 0.f, o1 = 0.f, o2 = 0.f;
    #pragma unroll 4
    for (int c = 0; c < NGD; c++) {
        float v = base[(size_t)c * LO];
        o0 = fmaf(v, pw_w[c], o0);
        o1 = fmaf(v, pw_w[NGD + c], o1);
        o2 = fmaf(v, pw_w[2 * NGD + c], o2);
    }
    int oy = pix / WO, ox = pix % WO;
    float ry = ((0.5f + (float)oy) / (float)HO) * 2.f - 1.f;
    float rx = ((0.5f + (float)ox) / (float)WO) * 2.f - 1.f;
    float posy = tanhf(o0) * (2.0f / (float)HO) + ry;
    float posx = tanhf(o1) * (2.0f / (float)WO) + rx;
    float gx = (posx + 1.f) * 0.5f * (float)(WW - 1);
    float gy = (posy + 1.f) * 0.5f * (float)(HH - 1);
    float sig = 1.f / (1.f + expf(-o2));
    float mod = 1.f / (1.f + expf(-sig));
    grid4[idx] = make_float4(gx, gy, mod, 0.f);
}

// ---------------- bilinear grid sample * modulation -> split bf16 ----------------
__global__ void sample_kernel(const float* __restrict__ x, const float4* __restrict__ grid4,
                              u16* __restrict__ xsh, u16* __restrict__ xsl) {
    int nc = blockIdx.x;
    int pix = blockIdx.y * blockDim.x + threadIdx.x;
    if (pix >= LO) return;
    int c = nc & (NGD - 1), n = nc >> 7;
    int b = n / GRP, g = n % GRP;
    float4 gq = grid4[(size_t)n * LO + pix];
    float gx = gq.x, gy = gq.y, mod = gq.z;
    float x0f = floorf(gx), y0f = floorf(gy);
    float x1f = x0f + 1.f, y1f = y0f + 1.f;
    const float* plane = x + ((size_t)(b * DIM + g * NGD + c)) * HWQ;

    float t00 = 0.f, t01 = 0.f, t10 = 0.f, t11 = 0.f;
    bool vx0 = (x0f >= 0.f) && (x0f <= (float)(WW - 1));
    bool vx1 = (x1f >= 0.f) && (x1f <= (float)(WW - 1));
    bool vy0 = (y0f >= 0.f) && (y0f <= (float)(HH - 1));
    bool vy1 = (y1f >= 0.f) && (y1f <= (float)(HH - 1));
    int xi0 = (int)fminf(fmaxf(x0f, 0.f), (float)(WW - 1));
    int xi1 = (int)fminf(fmaxf(x1f, 0.f), (float)(WW - 1));
    int yi0 = (int)fminf(fmaxf(y0f, 0.f), (float)(HH - 1));
    int yi1 = (int)fminf(fmaxf(y1f, 0.f), (float)(HH - 1));
    if (vy0 && vx0) t00 = plane[yi0 * WW + xi0];
    if (vy1 && vx0) t10 = plane[yi1 * WW + xi0];
    if (vy0 && vx1) t01 = plane[yi0 * WW + xi1];
    if (vy1 && vx1) t11 = plane[yi1 * WW + xi1];

    float v = t00 * (x1f - gx) * (y1f - gy)
            + t10 * (x1f - gx) * (gy - y0f)
            + t01 * (gx - x0f) * (y1f - gy)
            + t11 * (gx - x0f) * (gy - y0f);
    v *= mod;
    u16 hh, ll; split1(v, hh, ll);
    size_t o = ((size_t)(b * DIM + g * NGD + c)) * LO + pix;
    xsh[o] = hh; xsl[o] = ll;
}

// ---------------- launch ----------------
extern "C" void kernel_launch(void* const* d_in, const int* in_sizes, int n_in,
                              void* d_out, int out_size) {
    const float* x      = (const float*)d_in[0];
    const float* q_w    = (const float*)d_in[1];
    const float* kv_w   = (const float*)d_in[2];
    const float* proj_w = (const float*)d_in[3];
    const float* proj_b = (const float*)d_in[4];
    const float* dw_w   = (const float*)d_in[5];
    const float* dw_b   = (const float*)d_in[6];
    const float* bn_w   = (const float*)d_in[7];
    const float* bn_b   = (const float*)d_in[8];
    const float* bn_mean= (const float*)d_in[9];
    const float* bn_var = (const float*)d_in[10];
    const float* pw_w   = (const float*)d_in[11];
    float* out = (float*)d_out;

    float *q, *off; float4* grid;
    u16 *qh, *ql, *xh, *xl, *wqh, *wql, *wkh, *wkl, *wph, *wpl;
    u16 *xsh, *xsl, *kvh, *kvl, *ah, *al;
    cudaGetSymbolAddress((void**)&q,    d_q);
    cudaGetSymbolAddress((void**)&off,  d_off);
    cudaGetSymbolAddress((void**)&grid, d_grid);
    cudaGetSymbolAddress((void**)&qh,   d_qh);
    cudaGetSymbolAddress((void**)&ql,   d_ql);
    cudaGetSymbolAddress((void**)&xh,   d_xh);
    cudaGetSymbolAddress((void**)&xl,   d_xl);
    cudaGetSymbolAddress((void**)&wqh,  d_wqh);
    cudaGetSymbolAddress((void**)&wql,  d_wql);
    cudaGetSymbolAddress((void**)&wkh,  d_wkh);
    cudaGetSymbolAddress((void**)&wkl,  d_wkl);
    cudaGetSymbolAddress((void**)&wph,  d_wph);
    cudaGetSymbolAddress((void**)&wpl,  d_wpl);
    cudaGetSymbolAddress((void**)&xsh,  d_xsh);
    cudaGetSymbolAddress((void**)&xsl,  d_xsl);
    cudaGetSymbolAddress((void**)&kvh,  d_kvh);
    cudaGetSymbolAddress((void**)&kvl,  d_kvl);
    cudaGetSymbolAddress((void**)&ah,   d_ah);
    cudaGetSymbolAddress((void**)&al,   d_al);

    // pre-split x and weights
    {
        int n4 = BSZ * DIM * HWQ / 4;
        split_kernel<<<(n4 + 255) / 256, 256>>>(x, xh, xl, n4);
        int w4 = DIM * DIM / 4;
        split_kernel<<<(w4 + 255) / 256, 256>>>(q_w, wqh, wql, w4);
        split_kernel<<<(2 * w4 + 255) / 256, 256>>>(kv_w, wkh, wkl, 2 * w4);
        split_kernel<<<(w4 + 255) / 256, 256>>>(proj_w, wph, wpl, w4);
    }
    // K1: q = q_w @ x  -> f32 + split (Q split pre-scaled by SCALE)
    {
        dim3 g1((HWQ + 127) / 128, DIM / 128, BSZ);
        gemm_bf16<false, true, true><<<g1, 256>>>(wqh, wql, xh, xl, q, qh, ql,
                                                  nullptr, DIM, HWQ, 0, SCALE);
    }
    // K2: depthwise conv + bias + BN + gelu
    {
        int tot = BSZ * GRP * NGD * LO;
        dw_bn_gelu_kernel<<<(tot + 255) / 256, 256>>>(q, dw_w, dw_b, bn_w, bn_b,
                                                      bn_mean, bn_var, off);
    }
    // K3a: pointwise + grid
    {
        int tot = BSZ * GRP * LO;
        pw_grid_kernel<<<(tot + 255) / 256, 256>>>(off, pw_w, grid);
    }
    // K3b: bilinear sampling -> xs split
    {
        dim3 g((BSZ * GRP * NGD), (LO + 255) / 256);
        sample_kernel<<<g, 256>>>(x, grid, xsh, xsl);
    }
    // K4: kv = kv_w @ xs -> split only (k-half m0<384 uses 2-term)
    {
        dim3 g((LO + 127) / 128, (2 * DIM) / 128, BSZ);
        gemm_bf16<false, false, true><<<g, 256>>>(wkh, wkl, xsh, xsl, nullptr,
                                                  kvh, kvl, nullptr, 2 * DIM, LO, DIM, 1.0f);
    }
    // K5: fused attention (64q tiles, occ 3, peeled last tile) -> attn split
    {
        dim3 g(HWQ / 64, NH, BSZ);
        size_t smem = (size_t)(2 * 64 * AS + 2 * KVB) * sizeof(u16);  // 73728 B
        cudaFuncSetAttribute(attn_bf16, cudaFuncAttributeMaxDynamicSharedMemorySize, (int)smem);
        attn_bf16<<<g, 128, smem>>>(qh, ql, kvh, kvl, ah, al);
    }
    // K6: out = proj_w @ attn^T + proj_b  (3-term)
    {
        dim3 g1((HWQ + 127) / 128, DIM / 128, BSZ);
        gemm_bf16<true, true, false><<<g1, 256>>>(wph, wpl, ah, al, out,
                                                  nullptr, nullptr, proj_b, DIM, HWQ, 0, 1.0f);
    }
}